// round 2
// baseline (speedup 1.0000x reference)
#include <cuda_runtime.h>
#include <math.h>

// ---------------------------------------------------------------------------
// Problem constants (V=2, L=2, NP=NC=120000, D=128, S=100, NNEG=50, TEMP=0.5)
// ---------------------------------------------------------------------------
#define DD     128
#define SS     100
#define NNEGC  50
#define NNODE  120000
#define RPB    64            // rows per projection block
#define N_ANCHOR 3200        // 2 types * 4 (vi,li) * 4 (vj,lj) * 100
#define N_NEGROW 40000       // 2 types * 4 (vi,li) * 100 * 50
#define N_ROWS   43200       // total rows to project
#define N_SAMPLES 800        // 2 types * 4 keys * 100 anchors
#define TEMP_INV 2.0f

// Scratch (device globals: no runtime allocation allowed)
__device__ float g_proj[(size_t)N_ROWS * DD];   // ~22.1 MB
__device__ float g_loss[N_SAMPLES];
__device__ int   g_is64;

// ---------------------------------------------------------------------------
// Kernel 0: detect index dtype (int64 vs int32) once.
//   Reads first 64 values of neg_idx_p as int64; int32 data read this way
//   produces out-of-range values with overwhelming probability.
// ---------------------------------------------------------------------------
__global__ void detect_kernel(const void* __restrict__ neg_p)
{
    const long long* p = (const long long*)neg_p;
    int ok = 1;
    #pragma unroll 1
    for (int i = 0; i < 64; i++) {
        long long v = p[i];
        if (v < 0 || v >= NNODE) { ok = 0; break; }
    }
    g_is64 = ok;
}

// ---------------------------------------------------------------------------
// Kernel 1: gather + 2-layer MLP projection + l2norm for the 43200 used rows.
//   Row enumeration:
//     job < 3200 : anchor/pos rows.  job = ((key*4)+kk)*100 + s,
//                  key = t*4+vi*2+li; kk=0 self, kk=1 (1-vi,li),
//                  kk=2 (vi,1-li), kk=3 (1-vi,1-li); index = idx_t[vi,li,s],
//                  source slice = (vj,lj) of emb_t.
//     else       : cross negatives. j2 = (key*100+s)*50+n,
//                  index = neg_idx_t[vi,li,s,n], source = emb_other[vi,li].
// ---------------------------------------------------------------------------
__global__ void __launch_bounds__(256, 2) proj_kernel(
    const float* __restrict__ emb_p, const float* __restrict__ emb_c,
    const float* __restrict__ W1, const float* __restrict__ b1,
    const float* __restrict__ W2, const float* __restrict__ b2,
    const void* __restrict__ idx_p, const void* __restrict__ idx_c,
    const void* __restrict__ neg_p, const void* __restrict__ neg_c)
{
    extern __shared__ float smem[];
    float* Ws = smem;                 // 128*128 floats = 64 KB
    float* Xs = smem + DD * DD;       // 64*128 floats  = 32 KB
    __shared__ const float* srcPtr[RPB];

    const int tid = threadIdx.x;
    const int is64 = g_is64;

    // --- decode the 64 source-row pointers ---------------------------------
    if (tid < RPB) {
        int job = blockIdx.x * RPB + tid;
        const float* src;
        if (job < N_ANCHOR) {
            int t = job / 1600, rem = job % 1600;
            int vi = rem / 800;
            int li = (rem / 400) & 1;
            int kk = (rem / 100) & 3;
            int s  = rem % 100;
            const void* ib = t ? idx_c : idx_p;
            int off = (vi * 2 + li) * SS + s;
            int id = is64 ? (int)((const long long*)ib)[off]
                          : ((const int*)ib)[off];
            int vj = (kk & 1)  ? 1 - vi : vi;
            int lj = (kk >= 2) ? 1 - li : li;
            const float* emb = t ? emb_c : emb_p;
            src = emb + ((size_t)(vj * 2 + lj) * NNODE + id) * DD;
        } else {
            int j2 = job - N_ANCHOR;
            int t = j2 / 20000, rem = j2 % 20000;
            int vi = rem / 10000;
            int li = (rem / 5000) & 1;
            int s  = (rem % 5000) / NNEGC;
            int n  = rem % NNEGC;
            const void* nb = t ? neg_c : neg_p;
            int off = ((vi * 2 + li) * SS + s) * NNEGC + n;
            int id = is64 ? (int)((const long long*)nb)[off]
                          : ((const int*)nb)[off];
            const float* emb = t ? emb_p : emb_c;   // OTHER type
            src = emb + ((size_t)(vi * 2 + li) * NNODE + id) * DD;
        }
        srcPtr[tid] = src;
    }
    __syncthreads();

    float4* Ws4 = (float4*)Ws;
    float4* Xs4 = (float4*)Xs;

    // --- gather X (64 rows x 32 float4) and stage W1 -----------------------
    for (int i = tid; i < RPB * 32; i += 256)
        Xs4[i] = ((const float4*)srcPtr[i >> 5])[i & 31];
    for (int i = tid; i < DD * 32; i += 256)
        Ws4[i] = ((const float4*)W1)[i];
    __syncthreads();

    const int warp = tid >> 5, lane = tid & 31;
    const int r0 = warp * 8;          // each warp owns rows r0..r0+7

    float acc[8][4];

    // ---------------- Layer 1: H = relu(X @ W1 + b1) -----------------------
    {
        float4 bb = ((const float4*)b1)[lane];
        #pragma unroll
        for (int r = 0; r < 8; r++) {
            acc[r][0] = bb.x; acc[r][1] = bb.y; acc[r][2] = bb.z; acc[r][3] = bb.w;
        }
    }
    #pragma unroll 4
    for (int k = 0; k < DD; k++) {
        float4 w = Ws4[k * 32 + lane];
        #pragma unroll
        for (int r = 0; r < 8; r++) {
            float x = Xs[(r0 + r) * DD + k];
            acc[r][0] = fmaf(x, w.x, acc[r][0]);
            acc[r][1] = fmaf(x, w.y, acc[r][1]);
            acc[r][2] = fmaf(x, w.z, acc[r][2]);
            acc[r][3] = fmaf(x, w.w, acc[r][3]);
        }
    }
    // relu, write H back into this warp's own Xs rows (warp-private rows)
    #pragma unroll
    for (int r = 0; r < 8; r++) {
        float4 h = make_float4(fmaxf(acc[r][0], 0.f), fmaxf(acc[r][1], 0.f),
                               fmaxf(acc[r][2], 0.f), fmaxf(acc[r][3], 0.f));
        Xs4[(r0 + r) * 32 + lane] = h;
    }
    __syncthreads();                      // all warps done reading W1
    for (int i = tid; i < DD * 32; i += 256)
        Ws4[i] = ((const float4*)W2)[i];
    __syncthreads();

    // ---------------- Layer 2: Y = H @ W2 + b2 -----------------------------
    {
        float4 bb = ((const float4*)b2)[lane];
        #pragma unroll
        for (int r = 0; r < 8; r++) {
            acc[r][0] = bb.x; acc[r][1] = bb.y; acc[r][2] = bb.z; acc[r][3] = bb.w;
        }
    }
    #pragma unroll 4
    for (int k = 0; k < DD; k++) {
        float4 w = Ws4[k * 32 + lane];
        #pragma unroll
        for (int r = 0; r < 8; r++) {
            float x = Xs[(r0 + r) * DD + k];
            acc[r][0] = fmaf(x, w.x, acc[r][0]);
            acc[r][1] = fmaf(x, w.y, acc[r][1]);
            acc[r][2] = fmaf(x, w.z, acc[r][2]);
            acc[r][3] = fmaf(x, w.w, acc[r][3]);
        }
    }

    // ---------------- l2 normalize + store ---------------------------------
    float ssq[8];
    #pragma unroll
    for (int r = 0; r < 8; r++)
        ssq[r] = acc[r][0]*acc[r][0] + acc[r][1]*acc[r][1]
               + acc[r][2]*acc[r][2] + acc[r][3]*acc[r][3];
    #pragma unroll
    for (int off = 16; off > 0; off >>= 1) {
        #pragma unroll
        for (int r = 0; r < 8; r++)
            ssq[r] += __shfl_xor_sync(0xffffffffu, ssq[r], off);
    }
    size_t rowbase = (size_t)blockIdx.x * RPB + r0;
    #pragma unroll
    for (int r = 0; r < 8; r++) {
        float inv = 1.0f / fmaxf(sqrtf(ssq[r]), 1e-12f);
        float4 y = make_float4(acc[r][0]*inv, acc[r][1]*inv,
                               acc[r][2]*inv, acc[r][3]*inv);
        ((float4*)(g_proj + (rowbase + r) * DD))[lane] = y;
    }
}

// ---------------------------------------------------------------------------
// Kernel 2: per-anchor-sample InfoNCE term. One block per (type, vi, li, s).
//   152 dot products per block: 3 positives + 99 within-negs + 50 cross-negs.
// ---------------------------------------------------------------------------
__global__ void __launch_bounds__(128) loss_kernel()
{
    const int b   = blockIdx.x;              // 0..799
    const int key = b / 100;                 // t*4 + vi*2 + li
    const int s   = b % 100;
    const int tid = threadIdx.x;

    __shared__ float zs[DD];
    __shared__ float red_pos[128];
    __shared__ float red_neg[128];

    const float* zrow = g_proj + ((size_t)(key * 4 + 0) * SS + s) * DD;
    zs[tid] = zrow[tid];
    __syncthreads();

    float pos = 0.f, neg = 0.f;
    for (int v = tid; v < 152; v += 128) {
        const float* vec;
        bool is_pos = false;
        if (v < 3) {                                     // positives kk=1..3
            is_pos = true;
            vec = g_proj + ((size_t)(key * 4 + (v + 1)) * SS + s) * DD;
        } else if (v < 102) {                            // within-type negs
            int s2 = v - 3;
            if (s2 >= s) s2++;                           // skip diagonal
            vec = g_proj + ((size_t)(key * 4) * SS + s2) * DD;
        } else {                                         // cross-type negs
            int n = v - 102;
            vec = g_proj + (size_t)N_ANCHOR * DD
                + (((size_t)key * SS + s) * NNEGC + n) * DD;
        }
        const float4* v4 = (const float4*)vec;
        const float4* z4 = (const float4*)zs;
        float d = 0.f;
        #pragma unroll
        for (int i = 0; i < 32; i++) {
            float4 a = z4[i], c = v4[i];
            d += a.x*c.x + a.y*c.y + a.z*c.z + a.w*c.w;
        }
        float e = expf(d * TEMP_INV);
        if (is_pos) pos += e; else neg += e;
    }
    red_pos[tid] = pos;
    red_neg[tid] = neg;
    __syncthreads();
    #pragma unroll
    for (int off = 64; off > 0; off >>= 1) {
        if (tid < off) {
            red_pos[tid] += red_pos[tid + off];
            red_neg[tid] += red_neg[tid + off];
        }
        __syncthreads();
    }
    if (tid == 0) {
        float p = red_pos[0], n = red_neg[0];
        g_loss[b] = -logf(p / (p + n));
    }
}

// ---------------------------------------------------------------------------
// Kernel 3: deterministic final reduction
// ---------------------------------------------------------------------------
__global__ void __launch_bounds__(256) reduce_kernel(float* __restrict__ out)
{
    __shared__ float red[256];
    int tid = threadIdx.x;
    float a = 0.f;
    for (int i = tid; i < N_SAMPLES; i += 256) a += g_loss[i];
    red[tid] = a;
    __syncthreads();
    #pragma unroll
    for (int off = 128; off > 0; off >>= 1) {
        if (tid < off) red[tid] += red[tid + off];
        __syncthreads();
    }
    if (tid == 0) out[0] = red[0] / (float)N_SAMPLES;
}

// ---------------------------------------------------------------------------
// Launch: inputs in metadata order:
//   0 emb_p, 1 emb_c, 2 W1, 3 b1, 4 W2, 5 b2,
//   6 idx_p, 7 idx_c, 8 neg_idx_p, 9 neg_idx_c
// ---------------------------------------------------------------------------
extern "C" void kernel_launch(void* const* d_in, const int* in_sizes, int n_in,
                              void* d_out, int out_size)
{
    (void)in_sizes; (void)n_in; (void)out_size;

    const float* emb_p = (const float*)d_in[0];
    const float* emb_c = (const float*)d_in[1];
    const float* W1    = (const float*)d_in[2];
    const float* b1    = (const float*)d_in[3];
    const float* W2    = (const float*)d_in[4];
    const float* b2    = (const float*)d_in[5];
    const void*  idx_p = d_in[6];
    const void*  idx_c = d_in[7];
    const void*  neg_p = d_in[8];
    const void*  neg_c = d_in[9];
    float* out = (float*)d_out;

    const int smem_bytes = (DD * DD + RPB * DD) * (int)sizeof(float);  // 96 KB
    static int configured = 0;
    if (!configured) {
        cudaFuncSetAttribute(proj_kernel,
                             cudaFuncAttributeMaxDynamicSharedMemorySize,
                             smem_bytes);
        configured = 1;
    }

    detect_kernel<<<1, 1>>>(neg_p);
    proj_kernel<<<N_ROWS / RPB, 256, smem_bytes>>>(
        emb_p, emb_c, W1, b1, W2, b2, idx_p, idx_c, neg_p, neg_c);
    loss_kernel<<<N_SAMPLES, 128>>>();
    reduce_kernel<<<1, 256>>>(out);
}

// round 3
// speedup vs baseline: 1.2719x; 1.2719x over previous
#include <cuda_runtime.h>
#include <math.h>

// ---------------------------------------------------------------------------
// Problem constants (V=2, L=2, NP=NC=120000, D=128, S=100, NNEG=50, TEMP=0.5)
// ---------------------------------------------------------------------------
#define DD     128
#define SS     100
#define NNEGC  50
#define NNODE  120000
#define RPB    64            // rows per projection block
#define N_ANCHOR 3200        // 2 types * 4 (vi,li) * 4 (vj,lj) * 100
#define N_ROWS   43200       // total rows to project
#define N_SAMPLES 800        // 2 types * 4 keys * 100 anchors
#define TEMP_INV 2.0f

// Scratch (device globals: no runtime allocation allowed)
__device__ float g_proj[(size_t)N_ROWS * DD];   // ~22.1 MB
__device__ float g_loss[N_SAMPLES];
__device__ int   g_is64;

// ---------------------------------------------------------------------------
// Packed f32x2 helpers (sm_100+): one FFMA2 = two fp32 FMAs per issue slot.
// ---------------------------------------------------------------------------
__device__ __forceinline__ unsigned long long pack2(float a, float b) {
    unsigned long long r;
    asm("mov.b64 %0, {%1, %2};" : "=l"(r) : "f"(a), "f"(b));
    return r;
}
__device__ __forceinline__ void unpack2(unsigned long long v, float& a, float& b) {
    asm("mov.b64 {%0, %1}, %2;" : "=f"(a), "=f"(b) : "l"(v));
}
__device__ __forceinline__ unsigned long long ffma2(
    unsigned long long a, unsigned long long b, unsigned long long c) {
    unsigned long long d;
    asm("fma.rn.f32x2 %0, %1, %2, %3;" : "=l"(d) : "l"(a), "l"(b), "l"(c));
    return d;
}

// ---------------------------------------------------------------------------
// Kernel 0: detect index dtype (int64 vs int32) once.
// ---------------------------------------------------------------------------
__global__ void detect_kernel(const void* __restrict__ neg_p)
{
    const long long* p = (const long long*)neg_p;
    int ok = 1;
    #pragma unroll 1
    for (int i = 0; i < 64; i++) {
        long long v = p[i];
        if (v < 0 || v >= NNODE) { ok = 0; break; }
    }
    g_is64 = ok;
}

// ---------------------------------------------------------------------------
// Kernel 1: gather + 2-layer MLP projection + l2norm for the 43200 used rows.
// 256 threads, 64 rows/block; each warp owns 8 rows x 4 output cols (2 f32x2
// pairs). W staged in SMEM (64KB), X tile in SMEM (32KB).
// ---------------------------------------------------------------------------
__global__ void __launch_bounds__(256, 2) proj_kernel(
    const float* __restrict__ emb_p, const float* __restrict__ emb_c,
    const float* __restrict__ W1, const float* __restrict__ b1,
    const float* __restrict__ W2, const float* __restrict__ b2,
    const void* __restrict__ idx_p, const void* __restrict__ idx_c,
    const void* __restrict__ neg_p, const void* __restrict__ neg_c)
{
    extern __shared__ float smem[];
    float* Ws = smem;                 // 128*128 floats = 64 KB
    float* Xs = smem + DD * DD;       // 64*128 floats  = 32 KB
    __shared__ const float* srcPtr[RPB];

    const int tid = threadIdx.x;
    const int is64 = g_is64;

    // --- decode the 64 source-row pointers ---------------------------------
    if (tid < RPB) {
        int job = blockIdx.x * RPB + tid;
        const float* src;
        if (job < N_ANCHOR) {
            int t = job / 1600, rem = job % 1600;
            int vi = rem / 800;
            int li = (rem / 400) & 1;
            int kk = (rem / 100) & 3;
            int s  = rem % 100;
            const void* ib = t ? idx_c : idx_p;
            int off = (vi * 2 + li) * SS + s;
            int id = is64 ? (int)((const long long*)ib)[off]
                          : ((const int*)ib)[off];
            int vj = (kk & 1)  ? 1 - vi : vi;
            int lj = (kk >= 2) ? 1 - li : li;
            const float* emb = t ? emb_c : emb_p;
            src = emb + ((size_t)(vj * 2 + lj) * NNODE + id) * DD;
        } else {
            int j2 = job - N_ANCHOR;
            int t = j2 / 20000, rem = j2 % 20000;
            int vi = rem / 10000;
            int li = (rem / 5000) & 1;
            int s  = (rem % 5000) / NNEGC;
            int n  = rem % NNEGC;
            const void* nb = t ? neg_c : neg_p;
            int off = ((vi * 2 + li) * SS + s) * NNEGC + n;
            int id = is64 ? (int)((const long long*)nb)[off]
                          : ((const int*)nb)[off];
            const float* emb = t ? emb_p : emb_c;   // OTHER type
            src = emb + ((size_t)(vi * 2 + li) * NNODE + id) * DD;
        }
        srcPtr[tid] = src;
    }
    __syncthreads();

    float4* Ws4 = (float4*)Ws;
    float4* Xs4 = (float4*)Xs;

    // --- gather X (64 rows x 32 float4) and stage W1 -----------------------
    for (int i = tid; i < RPB * 32; i += 256)
        Xs4[i] = ((const float4*)srcPtr[i >> 5])[i & 31];
    for (int i = tid; i < DD * 32; i += 256)
        Ws4[i] = ((const float4*)W1)[i];
    __syncthreads();

    const int warp = tid >> 5, lane = tid & 31;
    const int r0 = warp * 8;          // each warp owns rows r0..r0+7

    const unsigned w_base = (unsigned)__cvta_generic_to_shared(Ws) + lane * 16u;
    const unsigned x_base = (unsigned)__cvta_generic_to_shared(Xs) + r0 * (DD * 4u);

    unsigned long long acc2[8][2];

    // ---------------- Layer 1: H = relu(X @ W1 + b1) -----------------------
    {
        float4 bb = ((const float4*)b1)[lane];
        unsigned long long b01 = pack2(bb.x, bb.y), b23 = pack2(bb.z, bb.w);
        #pragma unroll
        for (int r = 0; r < 8; r++) { acc2[r][0] = b01; acc2[r][1] = b23; }
    }
    #pragma unroll 4
    for (int k = 0; k < DD; k += 2) {
        unsigned long long wA0, wA1, wB0, wB1;
        unsigned wa = w_base + (unsigned)k * 512u;       // k*32 float4
        asm("ld.shared.v2.b64 {%0,%1}, [%2];" : "=l"(wA0), "=l"(wA1) : "r"(wa));
        asm("ld.shared.v2.b64 {%0,%1}, [%2];" : "=l"(wB0), "=l"(wB1) : "r"(wa + 512u));
        #pragma unroll
        for (int r = 0; r < 8; r++) {
            float x0, x1;
            unsigned xa = x_base + (unsigned)(r * DD + k) * 4u;
            asm("ld.shared.v2.f32 {%0,%1}, [%2];" : "=f"(x0), "=f"(x1) : "r"(xa));
            unsigned long long xx0 = pack2(x0, x0);
            unsigned long long xx1 = pack2(x1, x1);
            acc2[r][0] = ffma2(xx0, wA0, acc2[r][0]);
            acc2[r][1] = ffma2(xx0, wA1, acc2[r][1]);
            acc2[r][0] = ffma2(xx1, wB0, acc2[r][0]);
            acc2[r][1] = ffma2(xx1, wB1, acc2[r][1]);
        }
    }
    // relu, write H back into this warp's own Xs rows (warp-private rows)
    #pragma unroll
    for (int r = 0; r < 8; r++) {
        float a0, a1, a2, a3;
        unpack2(acc2[r][0], a0, a1);
        unpack2(acc2[r][1], a2, a3);
        float4 h = make_float4(fmaxf(a0, 0.f), fmaxf(a1, 0.f),
                               fmaxf(a2, 0.f), fmaxf(a3, 0.f));
        Xs4[(r0 + r) * 32 + lane] = h;
    }
    __syncthreads();                      // all warps done reading W1
    for (int i = tid; i < DD * 32; i += 256)
        Ws4[i] = ((const float4*)W2)[i];
    __syncthreads();

    // ---------------- Layer 2: Y = H @ W2 + b2 -----------------------------
    {
        float4 bb = ((const float4*)b2)[lane];
        unsigned long long b01 = pack2(bb.x, bb.y), b23 = pack2(bb.z, bb.w);
        #pragma unroll
        for (int r = 0; r < 8; r++) { acc2[r][0] = b01; acc2[r][1] = b23; }
    }
    #pragma unroll 4
    for (int k = 0; k < DD; k += 2) {
        unsigned long long wA0, wA1, wB0, wB1;
        unsigned wa = w_base + (unsigned)k * 512u;
        asm("ld.shared.v2.b64 {%0,%1}, [%2];" : "=l"(wA0), "=l"(wA1) : "r"(wa));
        asm("ld.shared.v2.b64 {%0,%1}, [%2];" : "=l"(wB0), "=l"(wB1) : "r"(wa + 512u));
        #pragma unroll
        for (int r = 0; r < 8; r++) {
            float x0, x1;
            unsigned xa = x_base + (unsigned)(r * DD + k) * 4u;
            asm("ld.shared.v2.f32 {%0,%1}, [%2];" : "=f"(x0), "=f"(x1) : "r"(xa));
            unsigned long long xx0 = pack2(x0, x0);
            unsigned long long xx1 = pack2(x1, x1);
            acc2[r][0] = ffma2(xx0, wA0, acc2[r][0]);
            acc2[r][1] = ffma2(xx0, wA1, acc2[r][1]);
            acc2[r][0] = ffma2(xx1, wB0, acc2[r][0]);
            acc2[r][1] = ffma2(xx1, wB1, acc2[r][1]);
        }
    }

    // ---------------- l2 normalize + store ---------------------------------
    float y[8][4];
    float ssq[8];
    #pragma unroll
    for (int r = 0; r < 8; r++) {
        unpack2(acc2[r][0], y[r][0], y[r][1]);
        unpack2(acc2[r][1], y[r][2], y[r][3]);
        ssq[r] = y[r][0]*y[r][0] + y[r][1]*y[r][1]
               + y[r][2]*y[r][2] + y[r][3]*y[r][3];
    }
    #pragma unroll
    for (int off = 16; off > 0; off >>= 1) {
        #pragma unroll
        for (int r = 0; r < 8; r++)
            ssq[r] += __shfl_xor_sync(0xffffffffu, ssq[r], off);
    }
    size_t rowbase = (size_t)blockIdx.x * RPB + r0;
    #pragma unroll
    for (int r = 0; r < 8; r++) {
        float inv = 1.0f / fmaxf(sqrtf(ssq[r]), 1e-12f);
        float4 o = make_float4(y[r][0]*inv, y[r][1]*inv,
                               y[r][2]*inv, y[r][3]*inv);
        ((float4*)(g_proj + (rowbase + r) * DD))[lane] = o;
    }
}

// ---------------------------------------------------------------------------
// Kernel 2: per-anchor-sample InfoNCE term. One block per (type, vi, li, s).
//   152 dot products per block: 3 positives + 99 within-negs + 50 cross-negs.
// ---------------------------------------------------------------------------
__global__ void __launch_bounds__(128) loss_kernel()
{
    const int b   = blockIdx.x;              // 0..799
    const int key = b / 100;                 // t*4 + vi*2 + li
    const int s   = b % 100;
    const int tid = threadIdx.x;

    __shared__ float zs[DD];
    __shared__ float red_pos[128];
    __shared__ float red_neg[128];

    const float* zrow = g_proj + ((size_t)(key * 4 + 0) * SS + s) * DD;
    zs[tid] = zrow[tid];
    __syncthreads();

    float pos = 0.f, neg = 0.f;
    for (int v = tid; v < 152; v += 128) {
        const float* vec;
        bool is_pos = false;
        if (v < 3) {                                     // positives kk=1..3
            is_pos = true;
            vec = g_proj + ((size_t)(key * 4 + (v + 1)) * SS + s) * DD;
        } else if (v < 102) {                            // within-type negs
            int s2 = v - 3;
            if (s2 >= s) s2++;                           // skip diagonal
            vec = g_proj + ((size_t)(key * 4) * SS + s2) * DD;
        } else {                                         // cross-type negs
            int n = v - 102;
            vec = g_proj + (size_t)N_ANCHOR * DD
                + (((size_t)key * SS + s) * NNEGC + n) * DD;
        }
        const float4* v4 = (const float4*)vec;
        const float4* z4 = (const float4*)zs;
        float d = 0.f;
        #pragma unroll
        for (int i = 0; i < 32; i++) {
            float4 a = z4[i], c = v4[i];
            d += a.x*c.x + a.y*c.y + a.z*c.z + a.w*c.w;
        }
        float e = expf(d * TEMP_INV);
        if (is_pos) pos += e; else neg += e;
    }
    red_pos[tid] = pos;
    red_neg[tid] = neg;
    __syncthreads();
    #pragma unroll
    for (int off = 64; off > 0; off >>= 1) {
        if (tid < off) {
            red_pos[tid] += red_pos[tid + off];
            red_neg[tid] += red_neg[tid + off];
        }
        __syncthreads();
    }
    if (tid == 0) {
        float p = red_pos[0], n = red_neg[0];
        g_loss[b] = -logf(p / (p + n));
    }
}

// ---------------------------------------------------------------------------
// Kernel 3: deterministic final reduction
// ---------------------------------------------------------------------------
__global__ void __launch_bounds__(256) reduce_kernel(float* __restrict__ out)
{
    __shared__ float red[256];
    int tid = threadIdx.x;
    float a = 0.f;
    for (int i = tid; i < N_SAMPLES; i += 256) a += g_loss[i];
    red[tid] = a;
    __syncthreads();
    #pragma unroll
    for (int off = 128; off > 0; off >>= 1) {
        if (tid < off) red[tid] += red[tid + off];
        __syncthreads();
    }
    if (tid == 0) out[0] = red[0] / (float)N_SAMPLES;
}

// ---------------------------------------------------------------------------
// Launch: inputs in metadata order:
//   0 emb_p, 1 emb_c, 2 W1, 3 b1, 4 W2, 5 b2,
//   6 idx_p, 7 idx_c, 8 neg_idx_p, 9 neg_idx_c
// ---------------------------------------------------------------------------
extern "C" void kernel_launch(void* const* d_in, const int* in_sizes, int n_in,
                              void* d_out, int out_size)
{
    (void)in_sizes; (void)n_in; (void)out_size;

    const float* emb_p = (const float*)d_in[0];
    const float* emb_c = (const float*)d_in[1];
    const float* W1    = (const float*)d_in[2];
    const float* b1    = (const float*)d_in[3];
    const float* W2    = (const float*)d_in[4];
    const float* b2    = (const float*)d_in[5];
    const void*  idx_p = d_in[6];
    const void*  idx_c = d_in[7];
    const void*  neg_p = d_in[8];
    const void*  neg_c = d_in[9];
    float* out = (float*)d_out;

    const int smem_bytes = (DD * DD + RPB * DD) * (int)sizeof(float);  // 96 KB
    static int configured = 0;
    if (!configured) {
        cudaFuncSetAttribute(proj_kernel,
                             cudaFuncAttributeMaxDynamicSharedMemorySize,
                             smem_bytes);
        configured = 1;
    }

    detect_kernel<<<1, 1>>>(neg_p);
    proj_kernel<<<N_ROWS / RPB, 256, smem_bytes>>>(
        emb_p, emb_c, W1, b1, W2, b2, idx_p, idx_c, neg_p, neg_c);
    loss_kernel<<<N_SAMPLES, 128>>>();
    reduce_kernel<<<1, 256>>>(out);
}